// round 6
// baseline (speedup 1.0000x reference)
#include <cuda_runtime.h>
#include <cstdint>

// VecLeadingZeroDetector108: for each row of 108 MSB-first bits (float 0/1),
// output the 7-bit MSB-first binary of the index of the first 1 (108 if none).
//
// Strategy: warp-cooperative early exit. Each warp owns R=8 rows. Rows are
// scanned in 32-float chunks (coalesced across lanes). Per phase, loads for
// ALL still-pending rows are issued back-to-back (MLP up to 8), then resolved
// via __ballot_sync. Expected read traffic ~197B/row instead of 432B/row.

#define N_BITS 108
#define N_OUT 7
#define ROWS_PER_WARP 8

__global__ __launch_bounds__(256, 8)
void lzd108_kernel(const float* __restrict__ X, float* __restrict__ out, int nrows)
{
    const int gwarp = (blockIdx.x * blockDim.x + threadIdx.x) >> 5;
    const int lane  = threadIdx.x & 31;

    const long long base_row = (long long)gwarp * ROWS_PER_WARP;
    if (base_row >= nrows) return;

    float v[ROWS_PER_WARP];
    unsigned pending = 0;           // warp-uniform bitmask of unresolved rows
    unsigned long long packed = 0;  // 8 x 7-bit idx values (warp-uniform)

    // ---- chunk 0: bits [0,32) of every row, loads issued back-to-back ----
    #pragma unroll
    for (int j = 0; j < ROWS_PER_WARP; j++) {
        long long r = base_row + j;
        // OOB rows: pretend bit0=1 so they resolve immediately and never load again
        v[j] = (r < nrows) ? __ldcs(X + (size_t)r * N_BITS + lane) : 1.0f;
    }
    #pragma unroll
    for (int j = 0; j < ROWS_PER_WARP; j++) {
        unsigned m = __ballot_sync(0xffffffffu, v[j] != 0.0f);
        int idx;
        if (m) {
            idx = __ffs(m) - 1;
        } else {
            idx = N_BITS;                 // provisional: all-zero so far
            pending |= (1u << j);
        }
        packed |= (unsigned long long)(idx & 127) << (7 * j);
    }

    // ---- chunks 1..3: only pending rows; loads first (MLP), then ballots ----
    #pragma unroll
    for (int c = 1; c < 4; c++) {
        if (!pending) break;              // warp-uniform early exit
        const int pos = c * 32 + lane;
        #pragma unroll
        for (int j = 0; j < ROWS_PER_WARP; j++) {
            if (pending & (1u << j)) {
                long long r = base_row + j;
                v[j] = (pos < N_BITS) ? __ldcs(X + (size_t)r * N_BITS + pos) : 0.0f;
            }
        }
        #pragma unroll
        for (int j = 0; j < ROWS_PER_WARP; j++) {
            if (pending & (1u << j)) {
                unsigned m = __ballot_sync(0xffffffffu, v[j] != 0.0f);
                if (m) {
                    int idx = c * 32 + __ffs(m) - 1;
                    // clear provisional 108 and set the real index
                    packed &= ~(127ULL << (7 * j));
                    packed |= (unsigned long long)(idx & 127) << (7 * j);
                    pending &= ~(1u << j);
                }
            }
        }
    }

    // ---- write 8 rows x 7 bits = 56 contiguous floats, coalesced ----
    const long long out_base  = base_row * N_OUT;
    const long long out_total = (long long)nrows * N_OUT;
    #pragma unroll
    for (int e_local = 0; e_local < ROWS_PER_WARP * N_OUT; e_local += 32) {
        int e = e_local + lane;
        if (e < ROWS_PER_WARP * N_OUT) {
            long long eg = out_base + e;
            if (eg < out_total) {
                int j = e / N_OUT;        // row within this warp's group
                int b = e % N_OUT;        // output bit position (MSB-first)
                int idx = (int)((packed >> (7 * j)) & 127ULL);
                out[eg] = (float)((idx >> (6 - b)) & 1);
            }
        }
    }
}

extern "C" void kernel_launch(void* const* d_in, const int* in_sizes, int n_in,
                              void* d_out, int out_size)
{
    const float* X = (const float*)d_in[0];
    float* out = (float*)d_out;

    const int nrows = in_sizes[0] / N_BITS;   // 2,000,000

    const int warps_needed = (nrows + ROWS_PER_WARP - 1) / ROWS_PER_WARP;
    const int threads = 256;                   // 8 warps per block
    const int warps_per_block = threads / 32;
    const int blocks = (warps_needed + warps_per_block - 1) / warps_per_block;

    lzd108_kernel<<<blocks, threads>>>(X, out, nrows);
}

// round 8
// speedup vs baseline: 1.0512x; 1.0512x over previous
#include <cuda_runtime.h>
#include <cstdint>

// VecLeadingZeroDetector108: for each row of 108 MSB-first bits (float 0/1),
// output the 7-bit MSB-first binary of the index of the first 1 (108 if none).
//
// R6 design: warp-cooperative early exit, 16 rows/warp (MLP=16 in phase 0),
// 32-bit element addressing (216M elems < 2^31), warp-uniform full-tile fast
// path, two scalar u64 accumulators for the 16x7-bit packed results.

#define N_BITS 108
#define N_OUT 7
#define R 16   // rows per warp

__global__ __launch_bounds__(256, 8)
void lzd108_kernel(const float* __restrict__ X, float* __restrict__ out, int nrows)
{
    const unsigned gwarp = (blockIdx.x * blockDim.x + threadIdx.x) >> 5;
    const unsigned lane  = threadIdx.x & 31;

    const unsigned base_row = gwarp * R;
    if (base_row >= (unsigned)nrows) return;

    const bool full = (base_row + R) <= (unsigned)nrows;   // warp-uniform
    const unsigned rowoff = base_row * N_BITS + lane;      // 32-bit element offset

    float v[R];
    unsigned pending = 0;                    // warp-uniform bitmask of unresolved rows
    unsigned long long p0 = 0, p1 = 0;       // 16 x 7-bit idx values (warp-uniform)

    // ---- phase 0: bits [0,32) of every row, 16 loads issued back-to-back ----
    if (full) {
        #pragma unroll
        for (int j = 0; j < R; j++)
            v[j] = __ldcs(X + rowoff + j * N_BITS);
    } else {
        #pragma unroll
        for (int j = 0; j < R; j++)
            v[j] = (base_row + j < (unsigned)nrows) ? __ldcs(X + rowoff + j * N_BITS) : 1.0f;
    }
    #pragma unroll
    for (int j = 0; j < R; j++) {
        unsigned m = __ballot_sync(0xffffffffu, v[j] != 0.0f);
        int idx;
        if (m) {
            idx = __ffs(m) - 1;
        } else {
            idx = N_BITS;                    // provisional: all-zero so far
            pending |= (1u << j);
        }
        const int s = 7 * (j & 7);
        if (j < 8) p0 |= (unsigned long long)idx << s;
        else       p1 |= (unsigned long long)idx << s;
    }

    // ---- phases 1..3: only pending rows; all loads first (MLP), then ballots ----
    #pragma unroll
    for (int c = 1; c < 4; c++) {
        if (!pending) break;                 // warp-uniform
        const unsigned pos  = c * 32 + lane;
        const bool in_row   = pos < N_BITS;  // only matters for c==3 (lane<12)
        #pragma unroll
        for (int j = 0; j < R; j++) {
            if (pending & (1u << j))
                v[j] = in_row ? __ldcs(X + rowoff + j * N_BITS + c * 32) : 0.0f;
        }
        #pragma unroll
        for (int j = 0; j < R; j++) {
            if (pending & (1u << j)) {
                unsigned m = __ballot_sync(0xffffffffu, v[j] != 0.0f);
                if (m) {
                    const unsigned long long idx = (unsigned long long)(c * 32 + __ffs(m) - 1);
                    const int s = 7 * (j & 7);
                    if (j < 8) p0 = (p0 & ~(127ULL << s)) | (idx << s);
                    else       p1 = (p1 & ~(127ULL << s)) | (idx << s);
                    pending &= ~(1u << j);
                }
            }
        }
    }

    // ---- write 16 rows x 7 bits = 112 contiguous floats, coalesced ----
    const unsigned out_base  = base_row * N_OUT;
    const unsigned out_total = (unsigned)nrows * N_OUT;
    #pragma unroll
    for (int e_local = 0; e_local < R * N_OUT; e_local += 32) {
        const unsigned e = e_local + lane;
        if (e < R * N_OUT) {
            const unsigned eg = out_base + e;
            if (eg < out_total) {
                const unsigned j = e / N_OUT;            // row within the group
                const unsigned b = e - j * N_OUT;        // output bit (MSB-first)
                const unsigned long long p = (j & 8) ? p1 : p0;
                const unsigned idx = (unsigned)((p >> (7 * (j & 7))) & 127ULL);
                __stcs(out + eg, (float)((idx >> (6 - b)) & 1u));
            }
        }
    }
}

extern "C" void kernel_launch(void* const* d_in, const int* in_sizes, int n_in,
                              void* d_out, int out_size)
{
    const float* X = (const float*)d_in[0];
    float* out = (float*)d_out;

    const int nrows = in_sizes[0] / N_BITS;   // 2,000,000

    const int warps_needed    = (nrows + R - 1) / R;
    const int threads         = 256;          // 8 warps per block
    const int warps_per_block = threads / 32;
    const int blocks = (warps_needed + warps_per_block - 1) / warps_per_block;

    lzd108_kernel<<<blocks, threads>>>(X, out, nrows);
}